// round 13
// baseline (speedup 1.0000x reference)
#include <cuda_runtime.h>

#define IN_DIM   2048
#define OUT_DIM  14951
#define THREADS  256
#define NB4      3737            // aligned float4 body chunks per row: (14951 - s) >> 2
#define EPS      1e-12f

// Build the shifted 4-window w = bias[4i+S .. 4i+S+3] from bv = bias4[i] and the
// next lane's bv (shfl_down).  'patch' lanes (no reliable shuffle source) reload
// the 0..2 needed neighbor scalars directly (callers guarantee in-bounds).
template<int S>
__device__ __forceinline__ float4 shift_window(float4 bv, const float* __restrict__ nb,
                                               bool patch)
{
    if (S == 0) return bv;
    float n0 = 0.f, n1 = 0.f, n2 = 0.f;
    if (S >= 1) n0 = __shfl_down_sync(0xFFFFFFFFu, bv.x, 1);
    if (S >= 2) n1 = __shfl_down_sync(0xFFFFFFFFu, bv.y, 1);
    if (S >= 3) n2 = __shfl_down_sync(0xFFFFFFFFu, bv.z, 1);
    if (patch) {
        if (S >= 1) n0 = __ldg(nb);
        if (S >= 2) n1 = __ldg(nb + 1);
        if (S >= 3) n2 = __ldg(nb + 2);
    }
    if (S == 1) return make_float4(bv.y, bv.z, bv.w, n0);
    if (S == 2) return make_float4(bv.z, bv.w, n0, n1);
    return make_float4(bv.w, n0, n1, n2);
}

template<int S>
__device__ __forceinline__ void epilogue_body(
    const float4* __restrict__ bias4, const float* __restrict__ bias,
    float* __restrict__ orow, float c, float4 ylo, float4 yhi,
    int t, int lane, int row)
{
    // ---- boundary chunk mi = 14 first: i = 3584 + t, valid iff i < NB4 ----
    {
        const int i  = 3584 + t;
        const int ii = (i < NB4) ? i : (NB4 - 1);      // clamp so whole warp loads/shuffles
        float4 bv = __ldg(bias4 + ii);
        // shuffle source unreliable for lane 31 and near the valid/invalid boundary
        float4 w = shift_window<S>(bv, bias + 4 * (ii + 1), lane == 31 || i >= NB4 - 1);
        if (i < NB4) {
            // (4i) mod 2048 = 0 block -> ylo (mi=14 even)
            float4 o4 = make_float4(fmaf(c, ylo.x, w.x), fmaf(c, ylo.y, w.y),
                                    fmaf(c, ylo.z, w.z), fmaf(c, ylo.w, w.w));
            __stcs(reinterpret_cast<float4*>(orow + S + 4 * i), o4);
        }
    }

    // ---- 14 CLEAN chunks (mi = 0..13): max i = 3583 < NB4, so no clamp, no
    // bounds test, unconditional store; lane-31 patch loads <= bias[14338]. ----
    int it0 = row % 14;            // rotation: decorrelates L2-line contention
#pragma unroll 1
    for (int cc = 0; cc < 14; ++cc) {
        int mi = it0 + cc;
        if (mi >= 14) mi -= 14;
        const int i = t + (mi << 8);
        float4 bv = __ldg(bias4 + i);
        float4 w  = shift_window<S>(bv, bias + 4 * (i + 1), lane == 31);
        float4 yv = (mi & 1) ? yhi : ylo;
        float4 o4 = make_float4(fmaf(c, yv.x, w.x), fmaf(c, yv.y, w.y),
                                fmaf(c, yv.z, w.z), fmaf(c, yv.w, w.w));
        __stcs(reinterpret_cast<float4*>(orow + S + 4 * i), o4);
    }
}

__global__ __launch_bounds__(THREADS)
void hc_kernel(const float* __restrict__ x,
               const float* __restrict__ scale,
               const float* __restrict__ bias,
               float* __restrict__ out)
{
    __shared__ alignas(16) float xch[IN_DIM];   // 8 KB: exchange, then shifted-y
    __shared__ float sred[THREADS / 32];
    __shared__ float sc;

    const int t    = threadIdx.x;
    const int row  = blockIdx.x;
    const int lane = t & 31;
    const int Q    = t >> 5;
    const int s    = row & 3;    // out + row*14951 + j is 16B-aligned iff j ≡ s (mod 4)

    float res[8];                // res[q] = element n = q*256 + t

    const float* __restrict__ xr = x + (size_t)row * IN_DIM;

    // ---- load (coalesced, evict-first) + sum of squares ----
    float ss = 0.f;
#pragma unroll
    for (int q = 0; q < 8; ++q) {
        float v = __ldcs(xr + q * THREADS + t);
        res[q] = v;
        ss += v * v;
    }
#pragma unroll
    for (int o = 16; o; o >>= 1) ss += __shfl_xor_sync(0xFFFFFFFFu, ss, o);
    if (lane == 0) sred[Q] = ss;
    __syncthreads();
    if (t == 0) {
        float tot = 0.f;
#pragma unroll
        for (int w = 0; w < THREADS / 32; ++w) tot += sred[w];
        sc = -scale[0] * rsqrtf(fmaxf(tot, EPS));
    }

    // ---- 3 register stages (bits 8..10 of n == bits of q) ----
#pragma unroll
    for (int B = 1; B < 8; B <<= 1) {
#pragma unroll
        for (int q = 0; q < 8; ++q) {
            if (!(q & B)) {
                float a0 = res[q], a1 = res[q | B];
                res[q]     = a0 + a1;
                res[q | B] = a0 - a1;
            }
        }
    }

    // ---- 5 shuffle stages (bits 0..4 of n == lane bits of t) ----
#pragma unroll
    for (int h = 1; h <= 16; h <<= 1) {
#pragma unroll
        for (int q = 0; q < 8; ++q) {
            float o = __shfl_xor_sync(0xFFFFFFFFu, res[q], h);
            res[q] = (t & h) ? (o - res[q]) : (res[q] + o);
        }
    }

    // ---- transpose A: bring warp-bits (5..7 of n) into register index u ----
#pragma unroll
    for (int q = 0; q < 8; ++q) xch[q * THREADS + t] = res[q];
    __syncthreads();
#pragma unroll
    for (int u = 0; u < 8; ++u) res[u] = xch[Q * THREADS + u * 32 + lane];

    // ---- 3 register stages over u (bits 5..7 of n) ----
#pragma unroll
    for (int B = 1; B < 8; B <<= 1) {
#pragma unroll
        for (int u = 0; u < 8; ++u) {
            if (!(u & B)) {
                float a0 = res[u], a1 = res[u | B];
                res[u]     = a0 + a1;
                res[u | B] = a0 - a1;
            }
        }
    }
    // now res[u] = y[Q*256 + u*32 + lane]

    // ---- transpose B (shift folded in): xch[k] = y[(k+s) & 2047] ----
    __syncthreads();
#pragma unroll
    for (int u = 0; u < 8; ++u) {
        int k = (Q * THREADS + u * 32 + lane - s) & (IN_DIM - 1);
        xch[k] = res[u];
    }
    __syncthreads();

    // thread t's two register-resident y float4s (j0 mod 2048 alternates 4t / 4t+1024)
    const float4 ylo = *reinterpret_cast<const float4*>(xch + 4 * t);
    const float4 yhi = *reinterpret_cast<const float4*>(xch + 4 * t + 1024);

    const float c = sc;
    float* __restrict__ orow = out + (size_t)row * OUT_DIM;

    // ---- head (j < s) and tail (j >= s+14948): scalar ----
    if (t < s) {
        int j = t;
        __stcs(orow + j, fmaf(c, xch[(j - s) & (IN_DIM - 1)], __ldg(bias + j)));
    }
    if (t < 3 - s) {
        int j = s + 4 * NB4 + t;                       // s + 14948 + t
        __stcs(orow + j, fmaf(c, xch[(4 * NB4 + t) & (IN_DIM - 1)], __ldg(bias + j)));
    }

    // ---- body: aligned LDG.128 bias + shuffle-shift + aligned STG.128 out ----
    const float4* __restrict__ bias4 = reinterpret_cast<const float4*>(bias);
    switch (s) {
        case 0: epilogue_body<0>(bias4, bias, orow, c, ylo, yhi, t, lane, row); break;
        case 1: epilogue_body<1>(bias4, bias, orow, c, ylo, yhi, t, lane, row); break;
        case 2: epilogue_body<2>(bias4, bias, orow, c, ylo, yhi, t, lane, row); break;
        default: epilogue_body<3>(bias4, bias, orow, c, ylo, yhi, t, lane, row); break;
    }
}

extern "C" void kernel_launch(void* const* d_in, const int* in_sizes, int n_in,
                              void* d_out, int out_size)
{
    const float* x     = (const float*)d_in[0];
    const float* scale = (const float*)d_in[1];
    const float* bias  = (const float*)d_in[2];
    float* out = (float*)d_out;

    const int batch = in_sizes[0] / IN_DIM;     // 4096
    hc_kernel<<<batch, THREADS>>>(x, scale, bias, out);
}

// round 14
// speedup vs baseline: 1.0031x; 1.0031x over previous
#include <cuda_runtime.h>

#define IN_DIM   2048
#define OUT_DIM  14951
#define THREADS  256
#define NB4      3737            // aligned float4 body chunks per row: (14951 - s) >> 2
#define EPS      1e-12f

// Build the shifted 4-window w = bias[4i+S .. 4i+S+3] from bv = bias4[i] and the
// next lane's bv (shfl_down). 'patch' lanes (no reliable shuffle source) reload
// the 0..2 needed neighbor scalars directly (callers guarantee in-bounds).
template<int S>
__device__ __forceinline__ float4 shift_window(float4 bv, const float* __restrict__ nb,
                                               bool patch)
{
    if (S == 0) return bv;
    float n0 = 0.f, n1 = 0.f, n2 = 0.f;
    if (S >= 1) n0 = __shfl_down_sync(0xFFFFFFFFu, bv.x, 1);
    if (S >= 2) n1 = __shfl_down_sync(0xFFFFFFFFu, bv.y, 1);
    if (S >= 3) n2 = __shfl_down_sync(0xFFFFFFFFu, bv.z, 1);
    if (patch) {
        if (S >= 1) n0 = __ldg(nb);
        if (S >= 2) n1 = __ldg(nb + 1);
        if (S >= 3) n2 = __ldg(nb + 2);
    }
    if (S == 1) return make_float4(bv.y, bv.z, bv.w, n0);
    if (S == 2) return make_float4(bv.z, bv.w, n0, n1);
    return make_float4(bv.w, n0, n1, n2);
}

template<int S>
__device__ __forceinline__ void epilogue_body(
    const float4* __restrict__ bias4, const float* __restrict__ bias,
    float* __restrict__ orow, float c, float4 ylo, float4 yhi,
    int t, int lane, int row)
{
    const int e0 = row % 7;        // rotation: decorrelates L2-line contention

    // ---- 7 clean EVEN chunks (mi = 0,2,..,12): i = t + 512e, yv = ylo ----
    // max i = 3327 < NB4; lane-31 patch loads <= bias[13314]: in bounds.
#pragma unroll 1
    for (int cc = 0; cc < 7; ++cc) {
        int e = e0 + cc;
        if (e >= 7) e -= 7;
        const int i = t + (e << 9);
        float4 bv = __ldg(bias4 + i);
        float4 w  = shift_window<S>(bv, bias + 4 * (i + 1), lane == 31);
        float4 o4 = make_float4(fmaf(c, ylo.x, w.x), fmaf(c, ylo.y, w.y),
                                fmaf(c, ylo.z, w.z), fmaf(c, ylo.w, w.w));
        __stcs(reinterpret_cast<float4*>(orow + S + 4 * i), o4);
    }

    // ---- 7 clean ODD chunks (mi = 1,3,..,13): i = t + 256 + 512e, yv = yhi ----
    // max i = 3583 < NB4; lane-31 patch loads <= bias[14338]: in bounds.
#pragma unroll 1
    for (int cc = 0; cc < 7; ++cc) {
        int e = e0 + cc;
        if (e >= 7) e -= 7;
        const int i = t + 256 + (e << 9);
        float4 bv = __ldg(bias4 + i);
        float4 w  = shift_window<S>(bv, bias + 4 * (i + 1), lane == 31);
        float4 o4 = make_float4(fmaf(c, yhi.x, w.x), fmaf(c, yhi.y, w.y),
                                fmaf(c, yhi.z, w.z), fmaf(c, yhi.w, w.w));
        __stcs(reinterpret_cast<float4*>(orow + S + 4 * i), o4);
    }

    // ---- boundary chunk mi = 14 LAST: i = 3584 + t, valid iff i < NB4 ----
    {
        const int i  = 3584 + t;
        const int ii = (i < NB4) ? i : (NB4 - 1);   // clamp: whole warp loads/shuffles
        float4 bv = __ldg(bias4 + ii);
        // shuffle source unreliable for lane 31 and near the valid/invalid boundary;
        // patch loads read bias[4*(ii+1) .. +S-1] <= bias[14950]: in bounds.
        float4 w = shift_window<S>(bv, bias + 4 * (ii + 1), lane == 31 || i >= NB4 - 1);
        if (i < NB4) {
            float4 o4 = make_float4(fmaf(c, ylo.x, w.x), fmaf(c, ylo.y, w.y),
                                    fmaf(c, ylo.z, w.z), fmaf(c, ylo.w, w.w));
            __stcs(reinterpret_cast<float4*>(orow + S + 4 * i), o4);
        }
    }
}

__global__ __launch_bounds__(THREADS)
void hc_kernel(const float* __restrict__ x,
               const float* __restrict__ scale,
               const float* __restrict__ bias,
               float* __restrict__ out)
{
    __shared__ alignas(16) float xch[IN_DIM];   // 8 KB: exchange, then shifted-y
    __shared__ float sred[THREADS / 32];
    __shared__ float sc;

    const int t    = threadIdx.x;
    const int row  = blockIdx.x;
    const int lane = t & 31;
    const int Q    = t >> 5;
    const int s    = row & 3;    // out + row*14951 + j is 16B-aligned iff j ≡ s (mod 4)

    float res[8];                // res[q] = element n = q*256 + t

    const float* __restrict__ xr = x + (size_t)row * IN_DIM;

    // ---- load (coalesced, evict-first) + sum of squares ----
    float ss = 0.f;
#pragma unroll
    for (int q = 0; q < 8; ++q) {
        float v = __ldcs(xr + q * THREADS + t);
        res[q] = v;
        ss += v * v;
    }
#pragma unroll
    for (int o = 16; o; o >>= 1) ss += __shfl_xor_sync(0xFFFFFFFFu, ss, o);
    if (lane == 0) sred[Q] = ss;
    __syncthreads();
    if (t == 0) {
        float tot = 0.f;
#pragma unroll
        for (int w = 0; w < THREADS / 32; ++w) tot += sred[w];
        sc = -scale[0] * rsqrtf(fmaxf(tot, EPS));
    }

    // ---- 3 register stages (bits 8..10 of n == bits of q) ----
#pragma unroll
    for (int B = 1; B < 8; B <<= 1) {
#pragma unroll
        for (int q = 0; q < 8; ++q) {
            if (!(q & B)) {
                float a0 = res[q], a1 = res[q | B];
                res[q]     = a0 + a1;
                res[q | B] = a0 - a1;
            }
        }
    }

    // ---- 5 shuffle stages (bits 0..4 of n == lane bits of t) ----
#pragma unroll
    for (int h = 1; h <= 16; h <<= 1) {
#pragma unroll
        for (int q = 0; q < 8; ++q) {
            float o = __shfl_xor_sync(0xFFFFFFFFu, res[q], h);
            res[q] = (t & h) ? (o - res[q]) : (res[q] + o);
        }
    }

    // ---- transpose A: bring warp-bits (5..7 of n) into register index u ----
#pragma unroll
    for (int q = 0; q < 8; ++q) xch[q * THREADS + t] = res[q];
    __syncthreads();
#pragma unroll
    for (int u = 0; u < 8; ++u) res[u] = xch[Q * THREADS + u * 32 + lane];

    // ---- 3 register stages over u (bits 5..7 of n) ----
#pragma unroll
    for (int B = 1; B < 8; B <<= 1) {
#pragma unroll
        for (int u = 0; u < 8; ++u) {
            if (!(u & B)) {
                float a0 = res[u], a1 = res[u | B];
                res[u]     = a0 + a1;
                res[u | B] = a0 - a1;
            }
        }
    }
    // now res[u] = y[Q*256 + u*32 + lane]

    // ---- transpose B (shift folded in): xch[k] = y[(k+s) & 2047] ----
    __syncthreads();
#pragma unroll
    for (int u = 0; u < 8; ++u) {
        int k = (Q * THREADS + u * 32 + lane - s) & (IN_DIM - 1);
        xch[k] = res[u];
    }
    __syncthreads();

    // thread t's two register-resident y float4s (j0 mod 2048 alternates 4t / 4t+1024)
    const float4 ylo = *reinterpret_cast<const float4*>(xch + 4 * t);
    const float4 yhi = *reinterpret_cast<const float4*>(xch + 4 * t + 1024);

    const float c = sc;
    float* __restrict__ orow = out + (size_t)row * OUT_DIM;

    // ---- head (j < s) and tail (j >= s+14948): scalar ----
    if (t < s) {
        int j = t;
        __stcs(orow + j, fmaf(c, xch[(j - s) & (IN_DIM - 1)], __ldg(bias + j)));
    }
    if (t < 3 - s) {
        int j = s + 4 * NB4 + t;                       // s + 14948 + t
        __stcs(orow + j, fmaf(c, xch[(4 * NB4 + t) & (IN_DIM - 1)], __ldg(bias + j)));
    }

    // ---- body: aligned LDG.128 bias + shuffle-shift + aligned STG.128 out ----
    const float4* __restrict__ bias4 = reinterpret_cast<const float4*>(bias);
    switch (s) {
        case 0: epilogue_body<0>(bias4, bias, orow, c, ylo, yhi, t, lane, row); break;
        case 1: epilogue_body<1>(bias4, bias, orow, c, ylo, yhi, t, lane, row); break;
        case 2: epilogue_body<2>(bias4, bias, orow, c, ylo, yhi, t, lane, row); break;
        default: epilogue_body<3>(bias4, bias, orow, c, ylo, yhi, t, lane, row); break;
    }
}

extern "C" void kernel_launch(void* const* d_in, const int* in_sizes, int n_in,
                              void* d_out, int out_size)
{
    const float* x     = (const float*)d_in[0];
    const float* scale = (const float*)d_in[1];
    const float* bias  = (const float*)d_in[2];
    float* out = (float*)d_out;

    const int batch = in_sizes[0] / IN_DIM;     // 4096
    hc_kernel<<<batch, THREADS>>>(x, scale, bias, out);
}

// round 15
// speedup vs baseline: 1.0416x; 1.0383x over previous
#include <cuda_runtime.h>

#define IN_DIM   2048
#define OUT_DIM  14951
#define THREADS  256
#define NB4      3737            // aligned float4 body chunks per row: (14951 - s) >> 2
#define EPS      1e-12f

// Build the shifted 4-window w = bias[4i+S .. 4i+S+3] from bv = bias4[i] and the
// next lane's bv (shfl_down). 'patch' lanes (no reliable shuffle source) reload
// the 0..2 needed neighbor scalars directly (callers guarantee in-bounds).
template<int S>
__device__ __forceinline__ float4 shift_window(float4 bv, const float* __restrict__ nb,
                                               bool patch)
{
    if (S == 0) return bv;
    float n0 = 0.f, n1 = 0.f, n2 = 0.f;
    if (S >= 1) n0 = __shfl_down_sync(0xFFFFFFFFu, bv.x, 1);
    if (S >= 2) n1 = __shfl_down_sync(0xFFFFFFFFu, bv.y, 1);
    if (S >= 3) n2 = __shfl_down_sync(0xFFFFFFFFu, bv.z, 1);
    if (patch) {
        if (S >= 1) n0 = __ldg(nb);
        if (S >= 2) n1 = __ldg(nb + 1);
        if (S >= 3) n2 = __ldg(nb + 2);
    }
    if (S == 1) return make_float4(bv.y, bv.z, bv.w, n0);
    if (S == 2) return make_float4(bv.z, bv.w, n0, n1);
    return make_float4(bv.w, n0, n1, n2);
}

template<int S>
__device__ __forceinline__ void epilogue_body(
    const float4* __restrict__ bias4, const float* __restrict__ bias,
    float* __restrict__ orow, float c, float4 ylo, float4 yhi,
    int t, int lane, int row)
{
    const int e0 = row % 7;        // rotation: decorrelates L2-line contention

    // ---- 7 clean EVEN chunks (i = t + 512e, yv = ylo); 1-deep bias prefetch ----
    // max i = 3327 < NB4; lane-31 patch loads <= bias[13314]: in bounds.
    {
        int e = e0;
        int i = t + (e << 9);
        float4 bv = __ldg(bias4 + i);
#pragma unroll 1
        for (int cc = 0; cc < 7; ++cc) {
            int en = e + 1;
            if (en >= 7) en -= 7;
            int inext = t + (en << 9);
            float4 bvn;
            if (cc < 6) bvn = __ldg(bias4 + inext);       // prefetch next chunk
            float4 w = shift_window<S>(bv, bias + 4 * (i + 1), lane == 31);
            float4 o4 = make_float4(fmaf(c, ylo.x, w.x), fmaf(c, ylo.y, w.y),
                                    fmaf(c, ylo.z, w.z), fmaf(c, ylo.w, w.w));
            __stcs(reinterpret_cast<float4*>(orow + S + 4 * i), o4);
            e = en; i = inext; bv = bvn;
        }
    }

    // ---- 7 clean ODD chunks (i = t + 256 + 512e, yv = yhi); prefetch likewise ----
    // max i = 3583 < NB4; lane-31 patch loads <= bias[14338]: in bounds.
    {
        int e = e0;
        int i = t + 256 + (e << 9);
        float4 bv = __ldg(bias4 + i);
#pragma unroll 1
        for (int cc = 0; cc < 7; ++cc) {
            int en = e + 1;
            if (en >= 7) en -= 7;
            int inext = t + 256 + (en << 9);
            float4 bvn;
            if (cc < 6) bvn = __ldg(bias4 + inext);
            float4 w = shift_window<S>(bv, bias + 4 * (i + 1), lane == 31);
            float4 o4 = make_float4(fmaf(c, yhi.x, w.x), fmaf(c, yhi.y, w.y),
                                    fmaf(c, yhi.z, w.z), fmaf(c, yhi.w, w.w));
            __stcs(reinterpret_cast<float4*>(orow + S + 4 * i), o4);
            e = en; i = inext; bv = bvn;
        }
    }

    // ---- boundary chunk mi = 14 LAST: i = 3584 + t, valid iff i < NB4 ----
    {
        const int i  = 3584 + t;
        const int ii = (i < NB4) ? i : (NB4 - 1);   // clamp: whole warp loads/shuffles
        float4 bv = __ldg(bias4 + ii);
        // shuffle source unreliable for lane 31 and near the valid/invalid boundary;
        // patch loads read bias[4*(ii+1) .. +S-1] <= bias[14950]: in bounds.
        float4 w = shift_window<S>(bv, bias + 4 * (ii + 1), lane == 31 || i >= NB4 - 1);
        if (i < NB4) {
            float4 o4 = make_float4(fmaf(c, ylo.x, w.x), fmaf(c, ylo.y, w.y),
                                    fmaf(c, ylo.z, w.z), fmaf(c, ylo.w, w.w));
            __stcs(reinterpret_cast<float4*>(orow + S + 4 * i), o4);
        }
    }
}

__global__ __launch_bounds__(THREADS)
void hc_kernel(const float* __restrict__ x,
               const float* __restrict__ scale,
               const float* __restrict__ bias,
               float* __restrict__ out)
{
    __shared__ alignas(16) float xch[IN_DIM];   // 8 KB: exchange, then shifted-y
    __shared__ float sred[THREADS / 32];
    __shared__ float sc;

    const int t    = threadIdx.x;
    const int row  = blockIdx.x;
    const int lane = t & 31;
    const int Q    = t >> 5;
    const int s    = row & 3;    // out + row*14951 + j is 16B-aligned iff j ≡ s (mod 4)

    float res[8];                // res[q] = element n = q*256 + t

    const float* __restrict__ xr = x + (size_t)row * IN_DIM;

    // ---- load (coalesced, evict-first) + sum of squares ----
    float ss = 0.f;
#pragma unroll
    for (int q = 0; q < 8; ++q) {
        float v = __ldcs(xr + q * THREADS + t);
        res[q] = v;
        ss += v * v;
    }
#pragma unroll
    for (int o = 16; o; o >>= 1) ss += __shfl_xor_sync(0xFFFFFFFFu, ss, o);
    if (lane == 0) sred[Q] = ss;   // visibility deferred to transpose-A's sync

    // ---- 3 register stages (bits 8..10 of n == bits of q) ----
#pragma unroll
    for (int B = 1; B < 8; B <<= 1) {
#pragma unroll
        for (int q = 0; q < 8; ++q) {
            if (!(q & B)) {
                float a0 = res[q], a1 = res[q | B];
                res[q]     = a0 + a1;
                res[q | B] = a0 - a1;
            }
        }
    }

    // ---- 5 shuffle stages (bits 0..4 of n == lane bits of t) ----
#pragma unroll
    for (int h = 1; h <= 16; h <<= 1) {
#pragma unroll
        for (int q = 0; q < 8; ++q) {
            float o = __shfl_xor_sync(0xFFFFFFFFu, res[q], h);
            res[q] = (t & h) ? (o - res[q]) : (res[q] + o);
        }
    }

    // ---- transpose A: bring warp-bits (5..7 of n) into register index u ----
#pragma unroll
    for (int q = 0; q < 8; ++q) xch[q * THREADS + t] = res[q];
    __syncthreads();               // covers xch AND sred
    if (t == 0) {
        float tot = 0.f;
#pragma unroll
        for (int w = 0; w < THREADS / 32; ++w) tot += sred[w];
        sc = -scale[0] * rsqrtf(fmaxf(tot, EPS));   // consumed after transpose-B sync
    }
#pragma unroll
    for (int u = 0; u < 8; ++u) res[u] = xch[Q * THREADS + u * 32 + lane];

    // ---- 3 register stages over u (bits 5..7 of n) ----
#pragma unroll
    for (int B = 1; B < 8; B <<= 1) {
#pragma unroll
        for (int u = 0; u < 8; ++u) {
            if (!(u & B)) {
                float a0 = res[u], a1 = res[u | B];
                res[u]     = a0 + a1;
                res[u | B] = a0 - a1;
            }
        }
    }
    // now res[u] = y[Q*256 + u*32 + lane]

    // ---- transpose B (shift folded in): xch[k] = y[(k+s) & 2047] ----
    __syncthreads();
#pragma unroll
    for (int u = 0; u < 8; ++u) {
        int k = (Q * THREADS + u * 32 + lane - s) & (IN_DIM - 1);
        xch[k] = res[u];
    }
    __syncthreads();

    // thread t's two register-resident y float4s (j0 mod 2048 alternates 4t / 4t+1024)
    const float4 ylo = *reinterpret_cast<const float4*>(xch + 4 * t);
    const float4 yhi = *reinterpret_cast<const float4*>(xch + 4 * t + 1024);

    const float c = sc;
    float* __restrict__ orow = out + (size_t)row * OUT_DIM;

    // ---- body: aligned LDG.128 bias + shuffle-shift + aligned STG.128 out ----
    const float4* __restrict__ bias4 = reinterpret_cast<const float4*>(bias);
    switch (s) {
        case 0: epilogue_body<0>(bias4, bias, orow, c, ylo, yhi, t, lane, row); break;
        case 1: epilogue_body<1>(bias4, bias, orow, c, ylo, yhi, t, lane, row); break;
        case 2: epilogue_body<2>(bias4, bias, orow, c, ylo, yhi, t, lane, row); break;
        default: epilogue_body<3>(bias4, bias, orow, c, ylo, yhi, t, lane, row); break;
    }

    // ---- head (j < s) and tail (j >= s+14948): scalar, after the streaming body ----
    if (t < s) {
        int j = t;
        __stcs(orow + j, fmaf(c, xch[(j - s) & (IN_DIM - 1)], __ldg(bias + j)));
    }
    if (t < 3 - s) {
        int j = s + 4 * NB4 + t;                       // s + 14948 + t
        __stcs(orow + j, fmaf(c, xch[(4 * NB4 + t) & (IN_DIM - 1)], __ldg(bias + j)));
    }
}

extern "C" void kernel_launch(void* const* d_in, const int* in_sizes, int n_in,
                              void* d_out, int out_size)
{
    const float* x     = (const float*)d_in[0];
    const float* scale = (const float*)d_in[1];
    const float* bias  = (const float*)d_in[2];
    float* out = (float*)d_out;

    const int batch = in_sizes[0] / IN_DIM;     // 4096
    hc_kernel<<<batch, THREADS>>>(x, scale, bias, out);
}